// round 3
// baseline (speedup 1.0000x reference)
#include <cuda_runtime.h>

#define HH 4096
#define WW 4096
#define NT 128
#define TW 512          // output columns per block (128 threads x 4 cols)
#define SEG 64          // output rows per block
#define PADL 528        // shared prefix-row floats: global cols [x0-8, x0+520)
#define PADL4 (PADL/4)  // 132 float4

// c_k = 1/(7*k^2) for k = 3,5,7,9,11,13,15
__device__ __constant__ float CKC[7] = {
    1.0f/63.0f, 1.0f/175.0f, 1.0f/343.0f, 1.0f/567.0f,
    1.0f/847.0f, 1.0f/1183.0f, 1.0f/1575.0f };

// One 16-prefix-row chunk = 4 subchunks of 4 rows.
// Per subchunk: prefetch next subchunk's 20 LDGs, publish 4 prefix rows to
// shared (double-buffered), 1 barrier, then 4-wide window math for 4 rows.
template<bool FIRST, bool LAST>
__device__ __forceinline__ void run_chunk(
    int tbase, int y0, int x0, int tid,
    const float* __restrict__ x, const float* __restrict__ mp,
    float* __restrict__ out,
    float4 (*sbuf)[4 * PADL4],
    float4 (&acc)[16],
    float (&cs)[5],
    const int (&g)[5],
    float (&vcur)[4][5])
{
    const float CK[7] = {
        1.0f/63.0f, 1.0f/175.0f, 1.0f/343.0f, 1.0f/567.0f,
        1.0f/847.0f, 1.0f/1183.0f, 1.0f/1575.0f };

#pragma unroll
    for (int s = 0; s < 4; s++) {
        // ---- prefetch loads for the NEXT subchunk ----
        float vnext[4][5];
        if (!LAST || s < 3) {
            int tn = tbase + 4 * (s + 1);
#pragma unroll
            for (int j = 0; j < 4; j++) {
                int ry = min(max(tn + j, 0), HH - 1);   // replicate pad (rows)
                const float* xr = x + (size_t)ry * WW;
#pragma unroll
                for (int q = 0; q < 5; q++)
                    vnext[j][q] = (q < 4 || tid < PADL - 4 * NT)
                                  ? __ldg(xr + g[q]) : 0.0f;
            }
        }

        // ---- publish 4 prefix rows for the CURRENT subchunk ----
        float* S = (float*)sbuf[s & 1];
#pragma unroll
        for (int j = 0; j < 4; j++) {
#pragma unroll
            for (int q = 0; q < 5; q++) {
                cs[q] += vcur[j][q];
                if (q < 4 || tid < PADL - 4 * NT)
                    S[j * PADL + q * NT + tid] = cs[q];
            }
        }
        __syncthreads();

        // ---- window math for 4 rows ----
#pragma unroll
        for (int j = 0; j < 4; j++) {
            const int i = 4 * s + j;                    // compile-time in chunk
            int t = tbase + i;

            // a[m] = prefix L at global col x0-8+4*tid+m, m=0..19
            float a[20];
            const float4* S4 = sbuf[s & 1] + j * PADL4;
#pragma unroll
            for (int q = 0; q < 5; q++) {
                float4 F = S4[tid + q];
                a[4 * q]     = F.x; a[4 * q + 1] = F.y;
                a[4 * q + 2] = F.z; a[4 * q + 3] = F.w;
            }

            // incremental horizontal window sums (4 cols), ring scatter
            float h0 = 0.0f;
#pragma unroll
            for (int r = 1; r <= 7; r++) {
                if (r == 1) h0 = a[7] + a[8] + a[9];
                else        h0 += a[8 - r] + a[8 + r];
                float h1 = h0 + a[9 + r]  - a[8 - r];
                float h2 = h1 + a[10 + r] - a[9 - r];
                float h3 = h2 + a[11 + r] - a[10 - r];
                float c  = CK[r - 1];
                if (!FIRST || i >= 7 + r) {             // target row t-r >= y0
                    int sp = (i - r + 9) & 15;
                    acc[sp].x += c * h0; acc[sp].y += c * h1;
                    acc[sp].z += c * h2; acc[sp].w += c * h3;
                }
                if (!FIRST || i + r >= 6) {             // target row t+r+1 >= y0
                    int sm = (i + r + 10) & 15;
                    acc[sm].x -= c * h0; acc[sm].y -= c * h1;
                    acc[sm].z -= c * h2; acc[sm].w -= c * h3;
                }
            }

            // row y = t-7 is complete after this prefix row
            int yr = t - 7;
            if ((!FIRST || i >= 14) && yr < y0 + SEG) {
                int sl = (i + 2) & 15;
                size_t off = (size_t)yr * WW + x0 + 4 * tid;
                float4 m = __ldg((const float4*)(mp + off));
                float4 o;
                o.x = acc[sl].x * m.x; o.y = acc[sl].y * m.y;
                o.z = acc[sl].z * m.z; o.w = acc[sl].w * m.w;
                *(float4*)(out + off) = o;
                acc[sl] = make_float4(0.f, 0.f, 0.f, 0.f);
            }
        }

        if (!LAST || s < 3) {
#pragma unroll
            for (int j = 0; j < 4; j++)
#pragma unroll
                for (int q = 0; q < 5; q++) vcur[j][q] = vnext[j][q];
        }
    }
}

__global__ __launch_bounds__(NT)
void meanconv_kernel(const float* __restrict__ x,
                     const float* __restrict__ mp,
                     float* __restrict__ out)
{
    __shared__ float4 sbuf[2][4 * PADL4];   // double-buffered 4-row prefix tiles

    const int tid = threadIdx.x;
    const int x0  = blockIdx.x * TW;
    const int y0  = blockIdx.y * SEG;

    float4 acc[16];
#pragma unroll
    for (int i = 0; i < 16; i++) acc[i] = make_float4(0.f, 0.f, 0.f, 0.f);

    // replicate pad (cols): clamped gather indices, fixed per block
    int g[5];
#pragma unroll
    for (int q = 0; q < 5; q++)
        g[q] = min(max(x0 - 8 + tid + q * NT, 0), WW - 1);

    float cs[5] = {0.f, 0.f, 0.f, 0.f, 0.f};

    // prologue: loads for chunk 0, subchunk 0 (prefix rows y0-7 .. y0-4)
    float vcur[4][5];
#pragma unroll
    for (int j = 0; j < 4; j++) {
        int ry = min(max(y0 - 7 + j, 0), HH - 1);
        const float* xr = x + (size_t)ry * WW;
#pragma unroll
        for (int q = 0; q < 5; q++)
            vcur[j][q] = (q < 4 || tid < PADL - 4 * NT) ? __ldg(xr + g[q]) : 0.0f;
    }

    run_chunk<true, false>(y0 - 7, y0, x0, tid, x, mp, out, sbuf, acc, cs, g, vcur);
#pragma unroll 1
    for (int c = 1; c < 4; c++)
        run_chunk<false, false>(y0 - 7 + 16 * c, y0, x0, tid, x, mp, out, sbuf,
                                acc, cs, g, vcur);
    run_chunk<false, true>(y0 - 7 + 64, y0, x0, tid, x, mp, out, sbuf,
                           acc, cs, g, vcur);
}

extern "C" void kernel_launch(void* const* d_in, const int* in_sizes, int n_in,
                              void* d_out, int out_size)
{
    const float* x  = (const float*)d_in[0];
    const float* mp = (const float*)d_in[1];
    float* out      = (float*)d_out;
    dim3 grid(WW / TW, HH / SEG);
    meanconv_kernel<<<grid, NT>>>(x, mp, out);
}